// round 10
// baseline (speedup 1.0000x reference)
#include <cuda_runtime.h>
#include <cuda_fp16.h>
#include <cstdint>

typedef __half fp16;
typedef unsigned int u32;
typedef unsigned long long u64;

#define BB 4
#define SS 2048
#define DD 1024
#define FF 4096
#define MM (BB * SS)

// ---------------- static device scratch (no allocations) -------------------
__device__ fp16 g_x16[MM*DD];
__device__ fp16 g_wq16[DD*DD], g_wk16[DD*DD], g_wv16[DD*DD], g_wo16[DD*DD];
__device__ fp16 g_w116[(size_t)DD*FF], g_w216[(size_t)FF*DD];
__device__ fp16 g_q16[MM*DD], g_k16[MM*DD];
__device__ float g_v[MM*DD];
__device__ fp16 g_vt16[MM*DD];
__device__ float g_sc[(size_t)BB*SS*SS];
__device__ fp16 g_P16[(size_t)BB*SS*SS];
__device__ fp16 g_c16[MM*DD];
__device__ float g_ao[MM*DD], g_x1[MM*DD];
__device__ fp16 g_x116[MM*DD];
__device__ fp16 g_h16[(size_t)MM*FF];
__device__ float g_ffo[MM*DD];

// ---------------- PTX helpers (base ISA — compute_103-safe) -----------------
__device__ __forceinline__ u32 smem_u32(const void* p) {
    u32 r;
    asm("{ .reg .u64 t; cvta.to.shared.u64 t, %1; cvt.u32.u64 %0, t; }" : "=r"(r) : "l"(p));
    return r;
}
__device__ __forceinline__ void cpa16(u32 d, const void* s) {
    asm volatile("cp.async.cg.shared.global [%0], [%1], 16;" :: "r"(d), "l"(s));
}
__device__ __forceinline__ void cpa_commit() { asm volatile("cp.async.commit_group;" ::: "memory"); }
template <int W> __device__ __forceinline__ void cpa_wait() {
    asm volatile("cp.async.wait_group %0;" :: "n"(W) : "memory");
}
__device__ __forceinline__ void ldsm4(u32& r0, u32& r1, u32& r2, u32& r3, u32 a) {
    asm volatile("ldmatrix.sync.aligned.m8n8.x4.shared.b16 {%0,%1,%2,%3}, [%4];"
        : "=r"(r0), "=r"(r1), "=r"(r2), "=r"(r3) : "r"(a));
}
__device__ __forceinline__ void mma16816(float* d, const u32* a, const u32* b) {
    asm volatile("mma.sync.aligned.m16n8k16.row.col.f32.f16.f16.f32 "
        "{%0,%1,%2,%3},{%4,%5,%6,%7},{%8,%9},{%0,%1,%2,%3};"
        : "+f"(d[0]), "+f"(d[1]), "+f"(d[2]), "+f"(d[3])
        : "r"(a[0]), "r"(a[1]), "r"(a[2]), "r"(a[3]), "r"(b[0]), "r"(b[1]));
}
__device__ __forceinline__ u32 packh2(float a, float b) {
    fp16 h0 = __float2half_rn(a), h1 = __float2half_rn(b);
    return (u32)__half_as_ushort(h0) | ((u32)__half_as_ushort(h1) << 16);
}

// ---------------------------------------------------------------------------
// fp16 mma.sync GEMM: C[M,N] = A[M,K] * B[N,K]^T, fp32 accum.
// Block 128x256, BK=64 (128B swizzled rows), 8 warps x (64x64) warp tiles,
// 3-stage cp.async pipeline. grid=(N/256, M/128, batch).
// Per k16: 8 ldmatrix.x4 feed 32 MMAs (4 MMA/ldsm) -> smem port at 50%.
// ---------------------------------------------------------------------------
#define GTPB 256
#define NSTAGE 3
#define STG 49152                    // A 16K | B 32K
#define SMEM_TOTAL (NSTAGE * STG)    // 144 KB

__global__ void __launch_bounds__(GTPB, 1) gemm_mma(
    const fp16* __restrict__ A, const fp16* __restrict__ B,
    const float* __restrict__ bias,
    float* __restrict__ outF, fp16* __restrict__ outH,
    int N, int K, long long sA, long long sB, long long sC,
    float scale, int relu)
{
    extern __shared__ __align__(1024) char smem[];
    const u32 sb = smem_u32(smem);
    const int tid = threadIdx.x;
    const int wid = tid >> 5, lane = tid & 31;

    const long long zb = blockIdx.z;
    const long long rowBase = (long long)blockIdx.y * 128;
    const long long colBase = (long long)blockIdx.x * 256;
    const fp16* Ar = A + zb * sA + rowBase * K;
    const fp16* Br = B + zb * sB + colBase * K;
    const int nt = K >> 6;

    // fill one 48KB stage: A 128 rows, B 256 rows, 128B/row, swizzled
    auto fill = [&](int t) {
        const u32 base = sb + (u32)(t % NSTAGE) * STG;
        const long long kof = (long long)t * 64;
#pragma unroll
        for (int i = 0; i < 4; i++) {          // A: 1024 16B chunks
            const int c = tid + i * GTPB;
            const int row = c >> 3, kc = c & 7;
            const u32 so = (u32)row * 128 + (((u32)kc * 16) ^ (((u32)row & 7) * 16));
            cpa16(base + so, Ar + (long long)row * K + kof + kc * 8);
        }
#pragma unroll
        for (int i = 0; i < 8; i++) {          // B: 2048 16B chunks
            const int c = tid + i * GTPB;
            const int row = c >> 3, kc = c & 7;
            const u32 so = (u32)row * 128 + (((u32)kc * 16) ^ (((u32)row & 7) * 16));
            cpa16(base + 16384 + so, Br + (long long)row * K + kof + kc * 8);
        }
    };

    fill(0); cpa_commit();
    fill(1); cpa_commit();

    float acc[4][8][4];
#pragma unroll
    for (int i = 0; i < 4; i++)
#pragma unroll
        for (int j = 0; j < 8; j++)
#pragma unroll
            for (int k = 0; k < 4; k++) acc[i][j][k] = 0.0f;

    const int mw = (wid >> 2) * 64;   // warp row offset (2 groups)
    const int nw = (wid & 3) * 64;    // warp col offset (4 groups)

    for (int t = 0; t < nt; t++) {
        if (t + 1 < nt) cpa_wait<1>(); else cpa_wait<0>();
        __syncthreads();                       // stage t visible; oldest free
        if (t + 2 < nt) { fill(t + 2); cpa_commit(); }

        const u32 base = sb + (u32)(t % NSTAGE) * STG;
#pragma unroll
        for (int k16 = 0; k16 < 4; k16++) {
            const u32 kb = (u32)k16 * 32;      // byte col of this k16
            // A fragments: 4 m16 tiles
            u32 a[4][4];
#pragma unroll
            for (int mi = 0; mi < 4; mi++) {
                const u32 row = (u32)(mw + mi * 16 + (lane & 15));
                const u32 kbyte = kb + ((u32)(lane >> 4) << 4);
                const u32 ad = base + row * 128 + (kbyte ^ ((row & 7) << 4));
                ldsm4(a[mi][0], a[mi][1], a[mi][2], a[mi][3], ad);
            }
            // B fragments: 8 n8 tiles via 4 x4-loads
            u32 b[8][2];
#pragma unroll
            for (int nj = 0; nj < 4; nj++) {
                const u32 g = (u32)(lane >> 3);
                const u32 nrow = (u32)(nw + nj * 16) + ((g >> 1) << 3) + (u32)(lane & 7);
                const u32 kbyte = kb + ((g & 1) << 4);
                const u32 bd = base + 16384 + nrow * 128 + (kbyte ^ ((nrow & 7) << 4));
                u32 q0, q1, q2, q3;
                ldsm4(q0, q1, q2, q3, bd);
                b[nj*2][0] = q0; b[nj*2][1] = q1; b[nj*2+1][0] = q2; b[nj*2+1][1] = q3;
            }
            // 32 MMAs
#pragma unroll
            for (int mi = 0; mi < 4; mi++)
#pragma unroll
                for (int ni = 0; ni < 8; ni++) mma16816(acc[mi][ni], a[mi], b[ni]);
        }
    }

    // ---- epilogue ----
    float* ofz = outF ? outF + zb * sC : (float*)0;
    fp16*  ohz = outH ? outH + zb * sC : (fp16*)0;
#pragma unroll
    for (int mi = 0; mi < 4; mi++) {
#pragma unroll
        for (int ni = 0; ni < 8; ni++) {
            const long long r0 = rowBase + mw + mi * 16 + (lane >> 2);
            const long long c0 = colBase + nw + ni * 8 + (lane & 3) * 2;
            float b0 = 0.0f, b1 = 0.0f;
            if (bias) { b0 = __ldg(bias + c0); b1 = __ldg(bias + c0 + 1); }
#pragma unroll
            for (int h = 0; h < 2; h++) {
                float v0 = acc[mi][ni][2*h]   * scale + b0;
                float v1 = acc[mi][ni][2*h+1] * scale + b1;
                if (relu) { v0 = fmaxf(v0, 0.0f); v1 = fmaxf(v1, 0.0f); }
                const long long off = (r0 + 8 * h) * N + c0;
                if (ofz) *(float2*)(ofz + off) = make_float2(v0, v1);
                if (ohz) *(u32*)(ohz + off) = packh2(v0, v1);
            }
        }
    }
}

// ---------------- elementwise kernels --------------------------------------
__global__ void __launch_bounds__(256) cvt_plain(
    const float4* __restrict__ in, fp16* __restrict__ o, int n4)
{
    const int i = blockIdx.x * 256 + threadIdx.x;
    if (i >= n4) return;
    float4 x = in[i];
    *(uint2*)(o + 4 * (size_t)i) = make_uint2(packh2(x.x, x.y), packh2(x.z, x.w));
}

// in [R,C] fp32 -> out [C,R] fp16. grid (C/32, R/32, batch), 256 thr.
__global__ void __launch_bounds__(256) transpose_cvt(
    const float* __restrict__ in, fp16* __restrict__ o,
    int R, int C, long long sIn, long long sOut)
{
    __shared__ float t[32][33];
    in += (long long)blockIdx.z * sIn;
    o  += (long long)blockIdx.z * sOut;
    const int r0 = blockIdx.y * 32, c0 = blockIdx.x * 32;
    const int tx = threadIdx.x & 31, ty = threadIdx.x >> 5;
#pragma unroll
    for (int i = 0; i < 32; i += 8)
        t[ty + i][tx] = in[(long long)(r0 + ty + i) * C + c0 + tx];
    __syncthreads();
#pragma unroll
    for (int i = 0; i < 32; i += 8)
        o[(long long)(c0 + ty + i) * R + r0 + tx] = __float2half_rn(t[tx][ty + i]);
}

// row softmax over 2048 -> fp16. grid = nrows, block = 256.
__global__ void __launch_bounds__(256) softmax_h(
    const float* __restrict__ S, fp16* __restrict__ P)
{
    const float* p = S + (size_t)blockIdx.x * 2048;
    fp16* ph = P + (size_t)blockIdx.x * 2048;
    const int tid = threadIdx.x;
    __shared__ float red[8];
    float v[8], m = -1e30f;
#pragma unroll
    for (int i = 0; i < 8; i++) { v[i] = p[tid + 256 * i]; m = fmaxf(m, v[i]); }
#pragma unroll
    for (int o = 16; o > 0; o >>= 1) m = fmaxf(m, __shfl_xor_sync(~0u, m, o));
    if ((tid & 31) == 0) red[tid >> 5] = m;
    __syncthreads();
    m = red[0];
#pragma unroll
    for (int i = 1; i < 8; i++) m = fmaxf(m, red[i]);
    float s = 0.0f;
#pragma unroll
    for (int i = 0; i < 8; i++) { v[i] = expf(v[i] - m); s += v[i]; }
#pragma unroll
    for (int o = 16; o > 0; o >>= 1) s += __shfl_xor_sync(~0u, s, o);
    __syncthreads();
    if ((tid & 31) == 0) red[tid >> 5] = s;
    __syncthreads();
    s = red[0]+red[1]+red[2]+red[3]+red[4]+red[5]+red[6]+red[7];
    const float inv = 1.0f / s;
#pragma unroll
    for (int i = 0; i < 8; i++)
        ph[tid + 256 * i] = __float2half_rn(v[i] * inv);
}

// out = LN(A+B)*g+be (fp32, optional fp16). grid = nrows (width 1024).
__global__ void __launch_bounds__(256) add_ln(
    const float* __restrict__ A, const float* __restrict__ Bv,
    const float* __restrict__ g, const float* __restrict__ be,
    float* __restrict__ outF, fp16* __restrict__ oh)
{
    const size_t base = (size_t)blockIdx.x * 1024;
    const int tid = threadIdx.x;
    __shared__ float r1[8], r2[8];
    float v[4], s = 0.0f, ss = 0.0f;
#pragma unroll
    for (int i = 0; i < 4; i++) {
        const int c = tid + 256 * i;
        v[i] = A[base + c] + Bv[base + c];
        s += v[i]; ss += v[i] * v[i];
    }
#pragma unroll
    for (int o = 16; o > 0; o >>= 1) {
        s  += __shfl_xor_sync(~0u, s, o);
        ss += __shfl_xor_sync(~0u, ss, o);
    }
    if ((tid & 31) == 0) { r1[tid >> 5] = s; r2[tid >> 5] = ss; }
    __syncthreads();
    s = 0.0f; ss = 0.0f;
#pragma unroll
    for (int i = 0; i < 8; i++) { s += r1[i]; ss += r2[i]; }
    const float mean = s * (1.0f / 1024.0f);
    const float rstd = rsqrtf(ss * (1.0f / 1024.0f) - mean * mean + 1e-5f);
#pragma unroll
    for (int i = 0; i < 4; i++) {
        const int c = tid + 256 * i;
        const float x = (v[i] - mean) * rstd * g[c] + be[c];
        outF[base + c] = x;
        if (oh) oh[base + c] = __float2half_rn(x);
    }
}

// ---------------------------------------------------------------------------
extern "C" void kernel_launch(void* const* d_in, const int* in_sizes, int n_in,
                              void* d_out, int out_size)
{
    (void)in_sizes; (void)n_in; (void)out_size;
    const float* x   = (const float*)d_in[0];
    const float* wq  = (const float*)d_in[1];  const float* bq = (const float*)d_in[2];
    const float* wk  = (const float*)d_in[3];  const float* bk = (const float*)d_in[4];
    const float* wv  = (const float*)d_in[5];  const float* bv = (const float*)d_in[6];
    const float* wo  = (const float*)d_in[7];  const float* bo = (const float*)d_in[8];
    const float* w1  = (const float*)d_in[9];  const float* b1 = (const float*)d_in[10];
    const float* w2  = (const float*)d_in[11]; const float* b2 = (const float*)d_in[12];
    const float* g1  = (const float*)d_in[13]; const float* be1 = (const float*)d_in[14];
    const float* g2  = (const float*)d_in[15]; const float* be2 = (const float*)d_in[16];
    float* out = (float*)d_out;

#define SYM(nm, s) void* nm; cudaGetSymbolAddress(&nm, s)
    SYM(x16, g_x16);
    SYM(wq16, g_wq16); SYM(wk16, g_wk16); SYM(wv16, g_wv16); SYM(wo16, g_wo16);
    SYM(w116, g_w116); SYM(w216, g_w216);
    SYM(q16, g_q16); SYM(k16, g_k16);
    SYM(v, g_v); SYM(vt16, g_vt16);
    SYM(sc, g_sc); SYM(P16, g_P16);
    SYM(c16, g_c16);
    SYM(ao, g_ao); SYM(x1, g_x1); SYM(x116, g_x116);
    SYM(h16, g_h16); SYM(ffo, g_ffo);
#undef SYM
#define Fo(p) ((float*)p)
#define Hp(p) ((fp16*)p)

    cudaFuncSetAttribute(gemm_mma, cudaFuncAttributeMaxDynamicSharedMemorySize, SMEM_TOTAL);

    // operand prep: x -> fp16; weights transposed -> [N,K] fp16
    cvt_plain<<<MM * DD / 4 / 256, 256>>>((const float4*)x, Hp(x16), MM * DD / 4);
    transpose_cvt<<<dim3(DD/32, DD/32, 1), 256>>>(wq, Hp(wq16), DD, DD, 0, 0);
    transpose_cvt<<<dim3(DD/32, DD/32, 1), 256>>>(wk, Hp(wk16), DD, DD, 0, 0);
    transpose_cvt<<<dim3(DD/32, DD/32, 1), 256>>>(wv, Hp(wv16), DD, DD, 0, 0);
    transpose_cvt<<<dim3(DD/32, DD/32, 1), 256>>>(wo, Hp(wo16), DD, DD, 0, 0);
    transpose_cvt<<<dim3(FF/32, DD/32, 1), 256>>>(w1, Hp(w116), DD, FF, 0, 0);
    transpose_cvt<<<dim3(DD/32, FF/32, 1), 256>>>(w2, Hp(w216), FF, DD, 0, 0);

    const dim3 gq(DD/256, MM/128, 1);
    // QKV projections (Q,K -> fp16; V -> fp32 then transpose to fp16)
    gemm_mma<<<gq, GTPB, SMEM_TOTAL>>>(Hp(x16), Hp(wq16), bq,
        (float*)0, Hp(q16), DD, DD, 0, 0, 0, 1.0f, 0);
    gemm_mma<<<gq, GTPB, SMEM_TOTAL>>>(Hp(x16), Hp(wk16), bk,
        (float*)0, Hp(k16), DD, DD, 0, 0, 0, 1.0f, 0);
    gemm_mma<<<gq, GTPB, SMEM_TOTAL>>>(Hp(x16), Hp(wv16), bv,
        Fo(v), (fp16*)0, DD, DD, 0, 0, 0, 1.0f, 0);
    transpose_cvt<<<dim3(DD/32, SS/32, BB), 256>>>(Fo(v), Hp(vt16),
        SS, DD, (long long)SS*DD, (long long)SS*DD);

    // scores = Q K^T / 32
    gemm_mma<<<dim3(SS/256, SS/128, BB), GTPB, SMEM_TOTAL>>>(
        Hp(q16), Hp(k16), (const float*)0,
        Fo(sc), (fp16*)0, SS, DD,
        (long long)SS*DD, (long long)SS*DD, (long long)SS*SS, 0.03125f, 0);

    softmax_h<<<BB * SS, 256>>>(Fo(sc), Hp(P16));

    // ctx = P @ V   (B = V^T [D,S])
    gemm_mma<<<dim3(DD/256, SS/128, BB), GTPB, SMEM_TOTAL>>>(
        Hp(P16), Hp(vt16), (const float*)0,
        (float*)0, Hp(c16), DD, SS,
        (long long)SS*SS, (long long)SS*DD, (long long)SS*DD, 1.0f, 0);

    // attn_out = ctx @ Wo + bo
    gemm_mma<<<gq, GTPB, SMEM_TOTAL>>>(Hp(c16), Hp(wo16), bo,
        Fo(ao), (fp16*)0, DD, DD, 0, 0, 0, 1.0f, 0);

    // x1 = LN(x + attn_out)
    add_ln<<<MM, 256>>>(x, Fo(ao), g1, be1, Fo(x1), Hp(x116));

    // h = relu(x1 @ W1 + b1)
    gemm_mma<<<dim3(FF/256, MM/128, 1), GTPB, SMEM_TOTAL>>>(
        Hp(x116), Hp(w116), b1,
        (float*)0, Hp(h16), FF, DD, 0, 0, 0, 1.0f, 1);

    // ff = h @ W2 + b2
    gemm_mma<<<gq, GTPB, SMEM_TOTAL>>>(Hp(h16), Hp(w216), b2,
        Fo(ffo), (fp16*)0, DD, FF, 0, 0, 0, 1.0f, 0);

    // out = LN(x1 + ff)
    add_ln<<<MM, 256>>>(Fo(x1), Fo(ffo), g2, be2, out, (fp16*)0);
}

// round 11
// speedup vs baseline: 1.1636x; 1.1636x over previous
#include <cuda_runtime.h>
#include <cuda_fp16.h>
#include <cstdint>

typedef __half fp16;
typedef unsigned int u32;
typedef unsigned long long u64;

#define BB 4
#define SS 2048
#define DD 1024
#define FF 4096
#define MM (BB * SS)
#define QKVN (3 * DD)   // 3072

// ---------------- static device scratch (no allocations) -------------------
__device__ fp16 g_x16[MM*DD];
__device__ fp16 g_wqkv16[(size_t)QKVN*DD];     // [3072,1024] rows: wq^T|wk^T|wv^T
__device__ float g_bqkv[QKVN];
__device__ fp16 g_wo16[DD*DD];
__device__ fp16 g_w116[(size_t)DD*FF], g_w216[(size_t)FF*DD];
__device__ fp16 g_qkv16[(size_t)MM*QKVN];      // [8192, 3072] = Q|K|V
__device__ fp16 g_vt16[MM*DD];                 // per batch [1024, 2048]
__device__ float g_sc[(size_t)BB*SS*SS];
__device__ fp16 g_P16[(size_t)BB*SS*SS];
__device__ fp16 g_c16[MM*DD];
__device__ float g_ao[MM*DD], g_x1[MM*DD];
__device__ fp16 g_x116[MM*DD];
__device__ fp16 g_h16[(size_t)MM*FF];
__device__ float g_ffo[MM*DD];

// ---------------- PTX helpers (base ISA — compute_103-safe) -----------------
__device__ __forceinline__ u32 smem_u32(const void* p) {
    u32 r;
    asm("{ .reg .u64 t; cvta.to.shared.u64 t, %1; cvt.u32.u64 %0, t; }" : "=r"(r) : "l"(p));
    return r;
}
__device__ __forceinline__ void cpa16(u32 d, const void* s) {
    asm volatile("cp.async.cg.shared.global [%0], [%1], 16;" :: "r"(d), "l"(s));
}
__device__ __forceinline__ void cpa_commit() { asm volatile("cp.async.commit_group;" ::: "memory"); }
template <int W> __device__ __forceinline__ void cpa_wait() {
    asm volatile("cp.async.wait_group %0;" :: "n"(W) : "memory");
}
__device__ __forceinline__ void ldsm4(u32& r0, u32& r1, u32& r2, u32& r3, u32 a) {
    asm volatile("ldmatrix.sync.aligned.m8n8.x4.shared.b16 {%0,%1,%2,%3}, [%4];"
        : "=r"(r0), "=r"(r1), "=r"(r2), "=r"(r3) : "r"(a));
}
__device__ __forceinline__ void mma16816(float* d, const u32* a, const u32* b) {
    asm volatile("mma.sync.aligned.m16n8k16.row.col.f32.f16.f16.f32 "
        "{%0,%1,%2,%3},{%4,%5,%6,%7},{%8,%9},{%0,%1,%2,%3};"
        : "+f"(d[0]), "+f"(d[1]), "+f"(d[2]), "+f"(d[3])
        : "r"(a[0]), "r"(a[1]), "r"(a[2]), "r"(a[3]), "r"(b[0]), "r"(b[1]));
}
__device__ __forceinline__ u32 packh2(float a, float b) {
    fp16 h0 = __float2half_rn(a), h1 = __float2half_rn(b);
    return (u32)__half_as_ushort(h0) | ((u32)__half_as_ushort(h1) << 16);
}

// ---------------------------------------------------------------------------
// fp16 mma.sync GEMM: C[M,N] = A * B^T (+bias, *scale, relu), fp32 accum.
// A rows stride lda, B rows stride ldb, C rows stride ldc.
// Block 128x128, BK=64, 8 warps x (64x32) warp tiles, 3-stage cp.async.
// grid=(N/128, M/128, batch). 2 CTAs/SM (96KB smem, <=128 regs).
// ---------------------------------------------------------------------------
#define GTPB 256
#define NSTAGE 3
#define STG 32768                    // A 16K | B 16K
#define SMEM_TOTAL (NSTAGE * STG)    // 96 KB

__global__ void __launch_bounds__(GTPB, 2) gemm_mma(
    const fp16* __restrict__ A, const fp16* __restrict__ B,
    const float* __restrict__ bias,
    float* __restrict__ outF, fp16* __restrict__ outH,
    int lda, int ldb, int ldc, int K,
    long long sA, long long sB, long long sC,
    float scale, int relu)
{
    extern __shared__ __align__(1024) char smem[];
    const u32 sb = smem_u32(smem);
    const int tid = threadIdx.x;
    const int wid = tid >> 5, lane = tid & 31;

    const long long zb = blockIdx.z;
    const long long rowBase = (long long)blockIdx.y * 128;
    const long long colBase = (long long)blockIdx.x * 128;
    const fp16* Ar = A + zb * sA + rowBase * lda;
    const fp16* Br = B + zb * sB + colBase * ldb;
    const int nt = K >> 6;

    auto fill = [&](int t) {
        const u32 base = sb + (u32)(t % NSTAGE) * STG;
        const long long kof = (long long)t * 64;
#pragma unroll
        for (int i = 0; i < 4; i++) {
            const int c = tid + i * GTPB;          // 0..1023
            const int row = c >> 3, kc = c & 7;
            const u32 so = (u32)row * 128 + (((u32)kc * 16) ^ (((u32)row & 7) * 16));
            cpa16(base + so,         Ar + (long long)row * lda + kof + kc * 8);
            cpa16(base + 16384 + so, Br + (long long)row * ldb + kof + kc * 8);
        }
    };

    fill(0); cpa_commit();
    fill(1); cpa_commit();

    float acc[4][4][4];
#pragma unroll
    for (int i = 0; i < 4; i++)
#pragma unroll
        for (int j = 0; j < 4; j++)
#pragma unroll
            for (int k = 0; k < 4; k++) acc[i][j][k] = 0.0f;

    const int mw = (wid >> 2) * 64;   // warp row offset (2 groups)
    const int nw = (wid & 3) * 32;    // warp col offset (4 groups)

    for (int t = 0; t < nt; t++) {
        if (t + 1 < nt) cpa_wait<1>(); else cpa_wait<0>();
        __syncthreads();
        if (t + 2 < nt) { fill(t + 2); cpa_commit(); }

        const u32 base = sb + (u32)(t % NSTAGE) * STG;
#pragma unroll
        for (int k16 = 0; k16 < 4; k16++) {
            const u32 kb = (u32)k16 * 32;
            u32 a[4][4];
#pragma unroll
            for (int mi = 0; mi < 4; mi++) {
                const u32 row = (u32)(mw + mi * 16 + (lane & 15));
                const u32 kbyte = kb + ((u32)(lane >> 4) << 4);
                const u32 ad = base + row * 128 + (kbyte ^ ((row & 7) << 4));
                ldsm4(a[mi][0], a[mi][1], a[mi][2], a[mi][3], ad);
            }
            u32 b[4][2];
#pragma unroll
            for (int nj = 0; nj < 2; nj++) {
                const u32 g = (u32)(lane >> 3);
                const u32 nrow = (u32)(nw + nj * 16) + ((g >> 1) << 3) + (u32)(lane & 7);
                const u32 kbyte = kb + ((g & 1) << 4);
                const u32 bd = base + 16384 + nrow * 128 + (kbyte ^ ((nrow & 7) << 4));
                u32 q0, q1, q2, q3;
                ldsm4(q0, q1, q2, q3, bd);
                b[nj*2][0] = q0; b[nj*2][1] = q1; b[nj*2+1][0] = q2; b[nj*2+1][1] = q3;
            }
#pragma unroll
            for (int mi = 0; mi < 4; mi++)
#pragma unroll
                for (int ni = 0; ni < 4; ni++) mma16816(acc[mi][ni], a[mi], b[ni]);
        }
    }

    // ---- epilogue ----
    float* ofz = outF ? outF + zb * sC : (float*)0;
    fp16*  ohz = outH ? outH + zb * sC : (fp16*)0;
#pragma unroll
    for (int mi = 0; mi < 4; mi++) {
#pragma unroll
        for (int ni = 0; ni < 4; ni++) {
            const long long r0 = rowBase + mw + mi * 16 + (lane >> 2);
            const long long c0 = colBase + nw + ni * 8 + (lane & 3) * 2;
            float b0 = 0.0f, b1 = 0.0f;
            if (bias) { b0 = __ldg(bias + c0); b1 = __ldg(bias + c0 + 1); }
#pragma unroll
            for (int h = 0; h < 2; h++) {
                float v0 = acc[mi][ni][2*h]   * scale + b0;
                float v1 = acc[mi][ni][2*h+1] * scale + b1;
                if (relu) { v0 = fmaxf(v0, 0.0f); v1 = fmaxf(v1, 0.0f); }
                const long long off = (r0 + 8 * h) * ldc + c0;
                if (ofz) *(float2*)(ofz + off) = make_float2(v0, v1);
                if (ohz) *(u32*)(ohz + off) = packh2(v0, v1);
            }
        }
    }
}

// ---------------- elementwise kernels --------------------------------------
__global__ void __launch_bounds__(256) cvt_plain(
    const float4* __restrict__ in, fp16* __restrict__ o, int n4)
{
    const int i = blockIdx.x * 256 + threadIdx.x;
    if (i >= n4) return;
    float4 x = in[i];
    *(uint2*)(o + 4 * (size_t)i) = make_uint2(packh2(x.x, x.y), packh2(x.z, x.w));
}

__global__ void concat3(const float* __restrict__ a, const float* __restrict__ b,
                        const float* __restrict__ c, float* __restrict__ o)
{
    const int i = blockIdx.x * 256 + threadIdx.x;
    if (i < DD) o[i] = a[i];
    else if (i < 2 * DD) o[i] = b[i - DD];
    else if (i < 3 * DD) o[i] = c[i - 2 * DD];
}

// fp32 in [R,C] -> out [C,R] fp16. grid (C/32, R/32), 256 thr.
__global__ void __launch_bounds__(256) transpose_cvt(
    const float* __restrict__ in, fp16* __restrict__ o, int R, int C)
{
    __shared__ float t[32][33];
    const int r0 = blockIdx.y * 32, c0 = blockIdx.x * 32;
    const int tx = threadIdx.x & 31, ty = threadIdx.x >> 5;
#pragma unroll
    for (int i = 0; i < 32; i += 8)
        t[ty + i][tx] = in[(long long)(r0 + ty + i) * C + c0 + tx];
    __syncthreads();
#pragma unroll
    for (int i = 0; i < 32; i += 8)
        o[(long long)(c0 + ty + i) * R + r0 + tx] = __float2half_rn(t[tx][ty + i]);
}

// fp16 in [R,C-view] (row stride ldin) -> out [C,R] fp16 (row stride R).
// grid (C/32, R/32, batch), 256 thr.
__global__ void __launch_bounds__(256) transpose_h(
    const fp16* __restrict__ in, fp16* __restrict__ o,
    int R, int C, int ldin, long long sIn, long long sOut)
{
    __shared__ fp16 t[32][34];
    in += (long long)blockIdx.z * sIn;
    o  += (long long)blockIdx.z * sOut;
    const int r0 = blockIdx.y * 32, c0 = blockIdx.x * 32;
    const int tx = threadIdx.x & 31, ty = threadIdx.x >> 5;
#pragma unroll
    for (int i = 0; i < 32; i += 8)
        t[ty + i][tx] = in[(long long)(r0 + ty + i) * ldin + c0 + tx];
    __syncthreads();
#pragma unroll
    for (int i = 0; i < 32; i += 8)
        o[(long long)(c0 + ty + i) * R + r0 + tx] = t[tx][ty + i];
}

// row softmax over 2048 -> fp16. grid = nrows, block = 256.
__global__ void __launch_bounds__(256) softmax_h(
    const float* __restrict__ S, fp16* __restrict__ P)
{
    const float* p = S + (size_t)blockIdx.x * 2048;
    fp16* ph = P + (size_t)blockIdx.x * 2048;
    const int tid = threadIdx.x;
    __shared__ float red[8];
    float v[8], m = -1e30f;
#pragma unroll
    for (int i = 0; i < 8; i++) { v[i] = p[tid + 256 * i]; m = fmaxf(m, v[i]); }
#pragma unroll
    for (int o = 16; o > 0; o >>= 1) m = fmaxf(m, __shfl_xor_sync(~0u, m, o));
    if ((tid & 31) == 0) red[tid >> 5] = m;
    __syncthreads();
    m = red[0];
#pragma unroll
    for (int i = 1; i < 8; i++) m = fmaxf(m, red[i]);
    float s = 0.0f;
#pragma unroll
    for (int i = 0; i < 8; i++) { v[i] = expf(v[i] - m); s += v[i]; }
#pragma unroll
    for (int o = 16; o > 0; o >>= 1) s += __shfl_xor_sync(~0u, s, o);
    __syncthreads();
    if ((tid & 31) == 0) red[tid >> 5] = s;
    __syncthreads();
    s = red[0]+red[1]+red[2]+red[3]+red[4]+red[5]+red[6]+red[7];
    const float inv = 1.0f / s;
#pragma unroll
    for (int i = 0; i < 8; i++)
        ph[tid + 256 * i] = __float2half_rn(v[i] * inv);
}

// out = LN(A+B)*g+be (fp32, optional fp16). grid = nrows (width 1024).
__global__ void __launch_bounds__(256) add_ln(
    const float* __restrict__ A, const float* __restrict__ Bv,
    const float* __restrict__ g, const float* __restrict__ be,
    float* __restrict__ outF, fp16* __restrict__ oh)
{
    const size_t base = (size_t)blockIdx.x * 1024;
    const int tid = threadIdx.x;
    __shared__ float r1[8], r2[8];
    float v[4], s = 0.0f, ss = 0.0f;
#pragma unroll
    for (int i = 0; i < 4; i++) {
        const int c = tid + 256 * i;
        v[i] = A[base + c] + Bv[base + c];
        s += v[i]; ss += v[i] * v[i];
    }
#pragma unroll
    for (int o = 16; o > 0; o >>= 1) {
        s  += __shfl_xor_sync(~0u, s, o);
        ss += __shfl_xor_sync(~0u, ss, o);
    }
    if ((tid & 31) == 0) { r1[tid >> 5] = s; r2[tid >> 5] = ss; }
    __syncthreads();
    s = 0.0f; ss = 0.0f;
#pragma unroll
    for (int i = 0; i < 8; i++) { s += r1[i]; ss += r2[i]; }
    const float mean = s * (1.0f / 1024.0f);
    const float rstd = rsqrtf(ss * (1.0f / 1024.0f) - mean * mean + 1e-5f);
#pragma unroll
    for (int i = 0; i < 4; i++) {
        const int c = tid + 256 * i;
        const float x = (v[i] - mean) * rstd * g[c] + be[c];
        outF[base + c] = x;
        if (oh) oh[base + c] = __float2half_rn(x);
    }
}

// ---------------------------------------------------------------------------
extern "C" void kernel_launch(void* const* d_in, const int* in_sizes, int n_in,
                              void* d_out, int out_size)
{
    (void)in_sizes; (void)n_in; (void)out_size;
    const float* x   = (const float*)d_in[0];
    const float* wq  = (const float*)d_in[1];  const float* bq = (const float*)d_in[2];
    const float* wk  = (const float*)d_in[3];  const float* bk = (const float*)d_in[4];
    const float* wv  = (const float*)d_in[5];  const float* bv = (const float*)d_in[6];
    const float* wo  = (const float*)d_in[7];  const float* bo = (const float*)d_in[8];
    const float* w1  = (const float*)d_in[9];  const float* b1 = (const float*)d_in[10];
    const float* w2  = (const float*)d_in[11]; const float* b2 = (const float*)d_in[12];
    const float* g1  = (const float*)d_in[13]; const float* be1 = (const float*)d_in[14];
    const float* g2  = (const float*)d_in[15]; const float* be2 = (const float*)d_in[16];
    float* out = (float*)d_out;

#define SYM(nm, s) void* nm; cudaGetSymbolAddress(&nm, s)
    SYM(x16, g_x16); SYM(wqkv16, g_wqkv16); SYM(bqkv, g_bqkv);
    SYM(wo16, g_wo16); SYM(w116, g_w116); SYM(w216, g_w216);
    SYM(qkv16, g_qkv16); SYM(vt16, g_vt16);
    SYM(sc, g_sc); SYM(P16, g_P16); SYM(c16, g_c16);
    SYM(ao, g_ao); SYM(x1, g_x1); SYM(x116, g_x116);
    SYM(h16, g_h16); SYM(ffo, g_ffo);
#undef SYM
#define Fo(p) ((float*)p)
#define Hp(p) ((fp16*)p)

    cudaFuncSetAttribute(gemm_mma, cudaFuncAttributeMaxDynamicSharedMemorySize, SMEM_TOTAL);

    // operand prep
    cvt_plain<<<MM * DD / 4 / 256, 256>>>((const float4*)x, Hp(x16), MM * DD / 4);
    transpose_cvt<<<dim3(DD/32, DD/32), 256>>>(wq, Hp(wqkv16), DD, DD);
    transpose_cvt<<<dim3(DD/32, DD/32), 256>>>(wk, Hp(wqkv16) + (size_t)DD*DD, DD, DD);
    transpose_cvt<<<dim3(DD/32, DD/32), 256>>>(wv, Hp(wqkv16) + (size_t)2*DD*DD, DD, DD);
    transpose_cvt<<<dim3(DD/32, DD/32), 256>>>(wo, Hp(wo16), DD, DD);
    transpose_cvt<<<dim3(FF/32, DD/32), 256>>>(w1, Hp(w116), DD, FF);
    transpose_cvt<<<dim3(DD/32, FF/32), 256>>>(w2, Hp(w216), FF, DD);
    concat3<<<(QKVN + 255) / 256, 256>>>(bq, bk, bv, Fo(bqkv));

    // fused QKV: [8192,1024] x [3072,1024]^T -> qkv16 [8192,3072]
    gemm_mma<<<dim3(QKVN/128, MM/128, 1), GTPB, SMEM_TOTAL>>>(
        Hp(x16), Hp(wqkv16), Fo(bqkv),
        (float*)0, Hp(qkv16), DD, DD, QKVN, DD, 0, 0, 0, 1.0f, 0);

    // V^T per batch: qkv16[:, 2048:3072] -> vt16 [1024, 2048]
    transpose_h<<<dim3(DD/32, SS/32, BB), 256>>>(
        Hp(qkv16) + 2 * DD, Hp(vt16), SS, DD, QKVN,
        (long long)SS * QKVN, (long long)SS * DD);

    // scores = Q K^T / 32  (strided views of qkv16)
    gemm_mma<<<dim3(SS/128, SS/128, BB), GTPB, SMEM_TOTAL>>>(
        Hp(qkv16), Hp(qkv16) + DD, (const float*)0,
        Fo(sc), (fp16*)0, QKVN, QKVN, SS, DD,
        (long long)SS*QKVN, (long long)SS*QKVN, (long long)SS*SS, 0.03125f, 0);

    softmax_h<<<BB * SS, 256>>>(Fo(sc), Hp(P16));

    // ctx = P @ V   (B = V^T [1024, 2048])
    gemm_mma<<<dim3(DD/128, SS/128, BB), GTPB, SMEM_TOTAL>>>(
        Hp(P16), Hp(vt16), (const float*)0,
        (float*)0, Hp(c16), SS, SS, DD, SS,
        (long long)SS*SS, (long long)SS*DD, (long long)SS*DD, 1.0f, 0);

    // attn_out = ctx @ Wo + bo
    gemm_mma<<<dim3(DD/128, MM/128, 1), GTPB, SMEM_TOTAL>>>(
        Hp(c16), Hp(wo16), bo,
        Fo(ao), (fp16*)0, DD, DD, DD, DD, 0, 0, 0, 1.0f, 0);

    // x1 = LN(x + attn_out)
    add_ln<<<MM, 256>>>(x, Fo(ao), g1, be1, Fo(x1), Hp(x116));

    // h = relu(x1 @ W1 + b1)
    gemm_mma<<<dim3(FF/128, MM/128, 1), GTPB, SMEM_TOTAL>>>(
        Hp(x116), Hp(w116), b1,
        (float*)0, Hp(h16), DD, DD, FF, DD, 0, 0, 0, 1.0f, 1);

    // ff = h @ W2 + b2
    gemm_mma<<<dim3(DD/128, MM/128, 1), GTPB, SMEM_TOTAL>>>(
        Hp(h16), Hp(w216), b2,
        Fo(ffo), (fp16*)0, FF, FF, DD, FF, 0, 0, 0, 1.0f, 0);

    // out = LN(x1 + ff)
    add_ln<<<MM, 256>>>(Fo(x1), Fo(ffo), g2, be2, out, (fp16*)0);
}

// round 12
// speedup vs baseline: 1.1850x; 1.0185x over previous
#include <cuda_runtime.h>
#include <cuda_fp16.h>
#include <cstdint>

typedef __half fp16;
typedef unsigned int u32;
typedef unsigned long long u64;

#define BB 4
#define SS 2048
#define DD 1024
#define FF 4096
#define MM (BB * SS)
#define QKVN (3 * DD)   // 3072

// ---------------- static device scratch (no allocations) -------------------
__device__ fp16 g_x16[MM*DD];
__device__ fp16 g_wqkv16[(size_t)QKVN*DD];     // [3072,1024] rows: wq^T|wk^T|wv^T
__device__ float g_bqkv[QKVN];
__device__ fp16 g_wo16[DD*DD];
__device__ fp16 g_w116[(size_t)DD*FF], g_w216[(size_t)FF*DD];
__device__ fp16 g_qkv16[(size_t)MM*QKVN];      // [8192, 3072] = Q|K|V
__device__ fp16 g_vt16[MM*DD];                 // per batch [1024, 2048]
__device__ float g_sc[(size_t)BB*SS*SS];
__device__ fp16 g_P16[(size_t)BB*SS*SS];
__device__ fp16 g_c16[MM*DD];
__device__ float g_ao[MM*DD], g_x1[MM*DD];
__device__ fp16 g_x116[MM*DD];
__device__ fp16 g_h16[(size_t)MM*FF];
__device__ float g_ffo[MM*DD];

// ---------------- PTX helpers (base ISA — compute_103-safe) -----------------
__device__ __forceinline__ u32 smem_u32(const void* p) {
    u32 r;
    asm("{ .reg .u64 t; cvta.to.shared.u64 t, %1; cvt.u32.u64 %0, t; }" : "=r"(r) : "l"(p));
    return r;
}
__device__ __forceinline__ void cpa16(u32 d, const void* s) {
    asm volatile("cp.async.cg.shared.global [%0], [%1], 16;" :: "r"(d), "l"(s));
}
__device__ __forceinline__ void cpa_commit() { asm volatile("cp.async.commit_group;" ::: "memory"); }
template <int W> __device__ __forceinline__ void cpa_wait() {
    asm volatile("cp.async.wait_group %0;" :: "n"(W) : "memory");
}
__device__ __forceinline__ void ldsm4(u32& r0, u32& r1, u32& r2, u32& r3, u32 a) {
    asm volatile("ldmatrix.sync.aligned.m8n8.x4.shared.b16 {%0,%1,%2,%3}, [%4];"
        : "=r"(r0), "=r"(r1), "=r"(r2), "=r"(r3) : "r"(a));
}
__device__ __forceinline__ void mma16816(float* d, const u32* a, const u32* b) {
    asm volatile("mma.sync.aligned.m16n8k16.row.col.f32.f16.f16.f32 "
        "{%0,%1,%2,%3},{%4,%5,%6,%7},{%8,%9},{%0,%1,%2,%3};"
        : "+f"(d[0]), "+f"(d[1]), "+f"(d[2]), "+f"(d[3])
        : "r"(a[0]), "r"(a[1]), "r"(a[2]), "r"(a[3]), "r"(b[0]), "r"(b[1]));
}
__device__ __forceinline__ u32 packh2(float a, float b) {
    fp16 h0 = __float2half_rn(a), h1 = __float2half_rn(b);
    return (u32)__half_as_ushort(h0) | ((u32)__half_as_ushort(h1) << 16);
}

// ---------------------------------------------------------------------------
// fp16 mma.sync GEMM: C[M,N] = A * B^T (+bias, *scale, relu), fp32 accum.
// A rows stride lda, B rows stride ldb, C rows stride ldc.
// Block 128x128, BK=64, 8 warps x (64x32) warp tiles, 3-stage cp.async.
// grid=(N/128, M/128, batch). 2 CTAs/SM (96KB smem, <=128 regs).
// ---------------------------------------------------------------------------
#define GTPB 256
#define NSTAGE 3
#define STG 32768                    // A 16K | B 16K
#define SMEM_TOTAL (NSTAGE * STG)    // 96 KB

__global__ void __launch_bounds__(GTPB, 2) gemm_mma(
    const fp16* __restrict__ A, const fp16* __restrict__ B,
    const float* __restrict__ bias,
    float* __restrict__ outF, fp16* __restrict__ outH,
    int lda, int ldb, int ldc, int K,
    long long sA, long long sB, long long sC,
    float scale, int relu)
{
    extern __shared__ __align__(1024) char smem[];
    const u32 sb = smem_u32(smem);
    const int tid = threadIdx.x;
    const int wid = tid >> 5, lane = tid & 31;

    const long long zb = blockIdx.z;
    const long long rowBase = (long long)blockIdx.y * 128;
    const long long colBase = (long long)blockIdx.x * 128;
    const fp16* Ar = A + zb * sA + rowBase * lda;
    const fp16* Br = B + zb * sB + colBase * ldb;
    const int nt = K >> 6;

    auto fill = [&](int t) {
        const u32 base = sb + (u32)(t % NSTAGE) * STG;
        const long long kof = (long long)t * 64;
#pragma unroll
        for (int i = 0; i < 4; i++) {
            const int c = tid + i * GTPB;          // 0..1023
            const int row = c >> 3, kc = c & 7;
            const u32 so = (u32)row * 128 + (((u32)kc * 16) ^ (((u32)row & 7) * 16));
            cpa16(base + so,         Ar + (long long)row * lda + kof + kc * 8);
            cpa16(base + 16384 + so, Br + (long long)row * ldb + kof + kc * 8);
        }
    };

    fill(0); cpa_commit();
    fill(1); cpa_commit();

    float acc[4][4][4];
#pragma unroll
    for (int i = 0; i < 4; i++)
#pragma unroll
        for (int j = 0; j < 4; j++)
#pragma unroll
            for (int k = 0; k < 4; k++) acc[i][j][k] = 0.0f;

    const int mw = (wid >> 2) * 64;   // warp row offset (2 groups)
    const int nw = (wid & 3) * 32;    // warp col offset (4 groups)

    for (int t = 0; t < nt; t++) {
        if (t + 1 < nt) cpa_wait<1>(); else cpa_wait<0>();
        __syncthreads();
        if (t + 2 < nt) { fill(t + 2); cpa_commit(); }

        const u32 base = sb + (u32)(t % NSTAGE) * STG;
#pragma unroll
        for (int k16 = 0; k16 < 4; k16++) {
            const u32 kb = (u32)k16 * 32;
            u32 a[4][4];
#pragma unroll
            for (int mi = 0; mi < 4; mi++) {
                const u32 row = (u32)(mw + mi * 16 + (lane & 15));
                const u32 kbyte = kb + ((u32)(lane >> 4) << 4);
                const u32 ad = base + row * 128 + (kbyte ^ ((row & 7) << 4));
                ldsm4(a[mi][0], a[mi][1], a[mi][2], a[mi][3], ad);
            }
            u32 b[4][2];
#pragma unroll
            for (int nj = 0; nj < 2; nj++) {
                const u32 g = (u32)(lane >> 3);
                const u32 nrow = (u32)(nw + nj * 16) + ((g >> 1) << 3) + (u32)(lane & 7);
                const u32 kbyte = kb + ((g & 1) << 4);
                const u32 bd = base + 16384 + nrow * 128 + (kbyte ^ ((nrow & 7) << 4));
                u32 q0, q1, q2, q3;
                ldsm4(q0, q1, q2, q3, bd);
                b[nj*2][0] = q0; b[nj*2][1] = q1; b[nj*2+1][0] = q2; b[nj*2+1][1] = q3;
            }
#pragma unroll
            for (int mi = 0; mi < 4; mi++)
#pragma unroll
                for (int ni = 0; ni < 4; ni++) mma16816(acc[mi][ni], a[mi], b[ni]);
        }
    }

    // ---- epilogue ----
    float* ofz = outF ? outF + zb * sC : (float*)0;
    fp16*  ohz = outH ? outH + zb * sC : (fp16*)0;
#pragma unroll
    for (int mi = 0; mi < 4; mi++) {
#pragma unroll
        for (int ni = 0; ni < 4; ni++) {
            const long long r0 = rowBase + mw + mi * 16 + (lane >> 2);
            const long long c0 = colBase + nw + ni * 8 + (lane & 3) * 2;
            float b0 = 0.0f, b1 = 0.0f;
            if (bias) { b0 = __ldg(bias + c0); b1 = __ldg(bias + c0 + 1); }
#pragma unroll
            for (int h = 0; h < 2; h++) {
                float v0 = acc[mi][ni][2*h]   * scale + b0;
                float v1 = acc[mi][ni][2*h+1] * scale + b1;
                if (relu) { v0 = fmaxf(v0, 0.0f); v1 = fmaxf(v1, 0.0f); }
                const long long off = (r0 + 8 * h) * ldc + c0;
                if (ofz) *(float2*)(ofz + off) = make_float2(v0, v1);
                if (ohz) *(u32*)(ohz + off) = packh2(v0, v1);
            }
        }
    }
}

// ---------------------------------------------------------------------------
// Fused operand prep: ONE launch does x->fp16, all 6 weight transposes
// (wq|wk|wv stacked into wqkv16, wo, w1, w2) and the bias concat.
// Block ranges:
//   [0,8192)        : x cvt        (MM*DD/4 elems, 1024 f4/blk)
//   [8192,12288)    : wq/wk/wv/wo  (4 x 1024 blocks of 32x32 tiles)
//   [12288,16384)   : w1           (grid 128x32)
//   [16384,20480)   : w2           (grid 32x128)
//   [20480,20492)   : bias concat  (3072 elems)
// ---------------------------------------------------------------------------
#define PREP_BLOCKS 20492

__device__ __forceinline__ void trans_tile(
    const float* __restrict__ in, fp16* __restrict__ o,
    int R, int C, int bx, int by, float (*t)[33], int tid)
{
    const int r0 = by * 32, c0 = bx * 32;
    const int tx = tid & 31, ty = tid >> 5;
#pragma unroll
    for (int i = 0; i < 32; i += 8)
        t[ty + i][tx] = in[(long long)(r0 + ty + i) * C + c0 + tx];
    __syncthreads();
#pragma unroll
    for (int i = 0; i < 32; i += 8)
        o[(long long)(c0 + ty + i) * R + r0 + tx] = __float2half_rn(t[tx][ty + i]);
}

__global__ void __launch_bounds__(256) prep_all(
    const float* __restrict__ x,
    const float* __restrict__ wq, const float* __restrict__ wk,
    const float* __restrict__ wv, const float* __restrict__ wo,
    const float* __restrict__ w1, const float* __restrict__ w2,
    const float* __restrict__ bq, const float* __restrict__ bk,
    const float* __restrict__ bv,
    fp16* __restrict__ x16, fp16* __restrict__ wqkv16, fp16* __restrict__ wo16,
    fp16* __restrict__ w116, fp16* __restrict__ w216, float* __restrict__ bqkv)
{
    __shared__ float t[32][33];
    const int b = blockIdx.x;
    const int tid = threadIdx.x;

    if (b < 8192) {                           // x fp32 -> fp16 (float4 lanes)
        const int i = b * 256 + tid;          // i < MM*DD/4 = 2097152
        float4 v = ((const float4*)x)[i];
        *(uint2*)(x16 + 4 * (size_t)i) = make_uint2(packh2(v.x, v.y), packh2(v.z, v.w));
    } else if (b < 12288) {                   // wq/wk/wv -> wqkv16, wo -> wo16
        const int r = b - 8192;
        const int w = r >> 10;                // 0..3
        const int q = r & 1023;
        const int bx = q & 31, by = q >> 5;   // grid (32, 32)
        const float* src = (w == 0) ? wq : (w == 1) ? wk : (w == 2) ? wv : wo;
        fp16* dst = (w < 3) ? (wqkv16 + (size_t)w * DD * DD) : wo16;
        trans_tile(src, dst, DD, DD, bx, by, t, tid);
    } else if (b < 16384) {                   // w1 [DD,FF] -> w116 [FF,DD]
        const int r = b - 12288;
        trans_tile(w1, w116, DD, FF, r & 127, r >> 7, t, tid);  // grid (128, 32)
    } else if (b < 20480) {                   // w2 [FF,DD] -> w216 [DD,FF]
        const int r = b - 16384;
        trans_tile(w2, w216, FF, DD, r & 31, r >> 5, t, tid);   // grid (32, 128)
    } else {                                  // bias concat
        const int i = (b - 20480) * 256 + tid;
        if (i < DD) bqkv[i] = bq[i];
        else if (i < 2 * DD) bqkv[i] = bk[i - DD];
        else if (i < 3 * DD) bqkv[i] = bv[i - 2 * DD];
    }
}

// fp16 in [R,C-view] (row stride ldin) -> out [C,R] fp16 (row stride R).
// grid (C/32, R/32, batch), 256 thr.
__global__ void __launch_bounds__(256) transpose_h(
    const fp16* __restrict__ in, fp16* __restrict__ o,
    int R, int C, int ldin, long long sIn, long long sOut)
{
    __shared__ fp16 t[32][34];
    in += (long long)blockIdx.z * sIn;
    o  += (long long)blockIdx.z * sOut;
    const int r0 = blockIdx.y * 32, c0 = blockIdx.x * 32;
    const int tx = threadIdx.x & 31, ty = threadIdx.x >> 5;
#pragma unroll
    for (int i = 0; i < 32; i += 8)
        t[ty + i][tx] = in[(long long)(r0 + ty + i) * ldin + c0 + tx];
    __syncthreads();
#pragma unroll
    for (int i = 0; i < 32; i += 8)
        o[(long long)(c0 + ty + i) * R + r0 + tx] = t[tx][ty + i];
}

// row softmax over 2048 -> fp16. grid = nrows, block = 256.
__global__ void __launch_bounds__(256) softmax_h(
    const float* __restrict__ S, fp16* __restrict__ P)
{
    const float* p = S + (size_t)blockIdx.x * 2048;
    fp16* ph = P + (size_t)blockIdx.x * 2048;
    const int tid = threadIdx.x;
    __shared__ float red[8];
    float v[8], m = -1e30f;
#pragma unroll
    for (int i = 0; i < 8; i++) { v[i] = p[tid + 256 * i]; m = fmaxf(m, v[i]); }
#pragma unroll
    for (int o = 16; o > 0; o >>= 1) m = fmaxf(m, __shfl_xor_sync(~0u, m, o));
    if ((tid & 31) == 0) red[tid >> 5] = m;
    __syncthreads();
    m = red[0];
#pragma unroll
    for (int i = 1; i < 8; i++) m = fmaxf(m, red[i]);
    float s = 0.0f;
#pragma unroll
    for (int i = 0; i < 8; i++) { v[i] = __expf(v[i] - m); s += v[i]; }
#pragma unroll
    for (int o = 16; o > 0; o >>= 1) s += __shfl_xor_sync(~0u, s, o);
    __syncthreads();
    if ((tid & 31) == 0) red[tid >> 5] = s;
    __syncthreads();
    s = red[0]+red[1]+red[2]+red[3]+red[4]+red[5]+red[6]+red[7];
    const float inv = 1.0f / s;
#pragma unroll
    for (int i = 0; i < 8; i++)
        ph[tid + 256 * i] = __float2half_rn(v[i] * inv);
}

// out = LN(A+B)*g+be (fp32, optional fp16). grid = nrows (width 1024).
__global__ void __launch_bounds__(256) add_ln(
    const float* __restrict__ A, const float* __restrict__ Bv,
    const float* __restrict__ g, const float* __restrict__ be,
    float* __restrict__ outF, fp16* __restrict__ oh)
{
    const size_t base = (size_t)blockIdx.x * 1024;
    const int tid = threadIdx.x;
    __shared__ float r1[8], r2[8];
    float v[4], s = 0.0f, ss = 0.0f;
#pragma unroll
    for (int i = 0; i < 4; i++) {
        const int c = tid + 256 * i;
        v[i] = A[base + c] + Bv[base + c];
        s += v[i]; ss += v[i] * v[i];
    }
#pragma unroll
    for (int o = 16; o > 0; o >>= 1) {
        s  += __shfl_xor_sync(~0u, s, o);
        ss += __shfl_xor_sync(~0u, ss, o);
    }
    if ((tid & 31) == 0) { r1[tid >> 5] = s; r2[tid >> 5] = ss; }
    __syncthreads();
    s = 0.0f; ss = 0.0f;
#pragma unroll
    for (int i = 0; i < 8; i++) { s += r1[i]; ss += r2[i]; }
    const float mean = s * (1.0f / 1024.0f);
    const float rstd = rsqrtf(ss * (1.0f / 1024.0f) - mean * mean + 1e-5f);
#pragma unroll
    for (int i = 0; i < 4; i++) {
        const int c = tid + 256 * i;
        const float x = (v[i] - mean) * rstd * g[c] + be[c];
        outF[base + c] = x;
        if (oh) oh[base + c] = __float2half_rn(x);
    }
}

// ---------------------------------------------------------------------------
extern "C" void kernel_launch(void* const* d_in, const int* in_sizes, int n_in,
                              void* d_out, int out_size)
{
    (void)in_sizes; (void)n_in; (void)out_size;
    const float* x   = (const float*)d_in[0];
    const float* wq  = (const float*)d_in[1];  const float* bq = (const float*)d_in[2];
    const float* wk  = (const float*)d_in[3];  const float* bk = (const float*)d_in[4];
    const float* wv  = (const float*)d_in[5];  const float* bv = (const float*)d_in[6];
    const float* wo  = (const float*)d_in[7];  const float* bo = (const float*)d_in[8];
    const float* w1  = (const float*)d_in[9];  const float* b1 = (const float*)d_in[10];
    const float* w2  = (const float*)d_in[11]; const float* b2 = (const float*)d_in[12];
    const float* g1  = (const float*)d_in[13]; const float* be1 = (const float*)d_in[14];
    const float* g2  = (const float*)d_in[15]; const float* be2 = (const float*)d_in[16];
    float* out = (float*)d_out;

#define SYM(nm, s) void* nm; cudaGetSymbolAddress(&nm, s)
    SYM(x16, g_x16); SYM(wqkv16, g_wqkv16); SYM(bqkv, g_bqkv);
    SYM(wo16, g_wo16); SYM(w116, g_w116); SYM(w216, g_w216);
    SYM(qkv16, g_qkv16); SYM(vt16, g_vt16);
    SYM(sc, g_sc); SYM(P16, g_P16); SYM(c16, g_c16);
    SYM(ao, g_ao); SYM(x1, g_x1); SYM(x116, g_x116);
    SYM(h16, g_h16); SYM(ffo, g_ffo);
#undef SYM
#define Fo(p) ((float*)p)
#define Hp(p) ((fp16*)p)

    cudaFuncSetAttribute(gemm_mma, cudaFuncAttributeMaxDynamicSharedMemorySize, SMEM_TOTAL);

    // ONE fused prep launch
    prep_all<<<PREP_BLOCKS, 256>>>(x, wq, wk, wv, wo, w1, w2, bq, bk, bv,
        Hp(x16), Hp(wqkv16), Hp(wo16), Hp(w116), Hp(w216), Fo(bqkv));

    // fused QKV: [8192,1024] x [3072,1024]^T -> qkv16 [8192,3072]
    gemm_mma<<<dim3(QKVN/128, MM/128, 1), GTPB, SMEM_TOTAL>>>(
        Hp(x16), Hp(wqkv16), Fo(bqkv),
        (float*)0, Hp(qkv16), DD, DD, QKVN, DD, 0, 0, 0, 1.0f, 0);

    // V^T per batch: qkv16[:, 2048:3072] -> vt16 [1024, 2048]
    transpose_h<<<dim3(DD/32, SS/32, BB), 256>>>(
        Hp(qkv16) + 2 * DD, Hp(vt16), SS, DD, QKVN,
        (long long)SS * QKVN, (long long)SS * DD);

    // scores = Q K^T / 32  (strided views of qkv16)
    gemm_mma<<<dim3(SS/128, SS/128, BB), GTPB, SMEM_TOTAL>>>(
        Hp(qkv16), Hp(qkv16) + DD, (const float*)0,
        Fo(sc), (fp16*)0, QKVN, QKVN, SS, DD,
        (long long)SS*QKVN, (long long)SS*QKVN, (long long)SS*SS, 0.03125f, 0);

    softmax_h<<<BB * SS, 256>>>(Fo(sc), Hp(P16));

    // ctx = P @ V   (B = V^T [1024, 2048])
    gemm_mma<<<dim3(DD/128, SS/128, BB), GTPB, SMEM_TOTAL>>>(
        Hp(P16), Hp(vt16), (const float*)0,
        (float*)0, Hp(c16), SS, SS, DD, SS,
        (long long)SS*SS, (long long)SS*DD, (long long)SS*DD, 1.0f, 0);

    // attn_out = ctx @ Wo + bo
    gemm_mma<<<dim3(DD/128, MM/128, 1), GTPB, SMEM_TOTAL>>>(
        Hp(c16), Hp(wo16), bo,
        Fo(ao), (fp16*)0, DD, DD, DD, DD, 0, 0, 0, 1.0f, 0);

    // x1 = LN(x + attn_out)
    add_ln<<<MM, 256>>>(x, Fo(ao), g1, be1, Fo(x1), Hp(x116));

    // h = relu(x1 @ W1 + b1)
    gemm_mma<<<dim3(FF/128, MM/128, 1), GTPB, SMEM_TOTAL>>>(
        Hp(x116), Hp(w116), b1,
        (float*)0, Hp(h16), DD, DD, FF, DD, 0, 0, 0, 1.0f, 1);

    // ff = h @ W2 + b2
    gemm_mma<<<dim3(DD/128, MM/128, 1), GTPB, SMEM_TOTAL>>>(
        Hp(h16), Hp(w216), b2,
        Fo(ffo), (fp16*)0, FF, FF, DD, FF, 0, 0, 0, 1.0f, 0);

    // out = LN(x1 + ff)
    add_ln<<<MM, 256>>>(Fo(x1), Fo(ffo), g2, be2, out, (fp16*)0);
}